// round 7
// baseline (speedup 1.0000x reference)
#include <cuda_runtime.h>
#include <cuda_bf16.h>

// StateSpaceLayer: out[b,t,r,c] = sum_{j<=t} A[r]^(t-j) * x[b,j,r,c]
// == per-(b,r,c) linear recurrence y_t = A[r]*y_{t-1} + x_t.
// x, out: (B,SEQ,D,D) fp32; A: (D,) fp32.  B=4, SEQ=512, D=64.
//
// R7: proven memory pattern (scalar LDG.32, warp = 32 contiguous c-lanes of
// one chunk) with restructured block internals:
//   - thread-parallel carry combine: each thread Horner-folds the chunk-end
//     values below it (parallel, ~16 LDS + 16 FMA) instead of a single-warp
//     530-cycle serial chain; eliminates one barrier per half.
//   - half-1 loads issued BEFORE the half-0 barrier, so barrier+combine+store
//     of h0 run with 16 loads/thread in flight (double-buffered s_end).
// 2 barriers per block total (was 4), both covered by in-flight memory.

#define SEQ   512
#define D     64
#define LCH   16            // timesteps per chunk (registers)
#define NC    16            // chunks per half
#define HALF  (NC*LCH)      // 256 timesteps per half
#define CH    32            // c-lanes per block (half of D)
#define CHP   33            // padded row to kill bank conflicts
#define TPB   (NC*CH)       // 512 threads
#define TS    (D*D)         // timestep stride in floats

__global__ __launch_bounds__(TPB, 2)
void ssm_scan_kernel(const float* __restrict__ x,
                     const float* __restrict__ A,
                     float* __restrict__ out)
{
    // grid = B * D * 2 : block covers (b, r, c-half)
    const int bid   = blockIdx.x;
    const int chalf = bid & 1;
    const int r     = (bid >> 1) & (D - 1);
    const int b     = bid >> 7;

    const int tid = threadIdx.x;
    const int cl  = tid & (CH - 1);      // c-lane
    const int k   = tid >> 5;            // chunk index 0..NC-1

    const float a = fmaxf(A[r], 1e-6f);  // reference clips at EPS=1e-6
    const float a2  = a * a;
    const float a4  = a2 * a2;
    const float a8  = a4 * a4;
    const float a16 = a8 * a8;           // per-chunk decay

    const long base = ((long)(b * SEQ + k * LCH) * D + r) * D + chalf * CH + cl;
    const float* __restrict__ xp0 = x + base;
    const float* __restrict__ xp1 = xp0 + (long)HALF * TS;

    __shared__ float s_end[2][NC][CHP];  // chunk-end partials, double-buffered
    __shared__ float s_c0[CH];           // inclusive carry of half 0

    // ---- half 0: load + local scan ----
    float v0[LCH];
    #pragma unroll
    for (int i = 0; i < LCH; i++)
        v0[i] = xp0[(long)i * TS];
    #pragma unroll
    for (int i = 1; i < LCH; i++)
        v0[i] = fmaf(a, v0[i - 1], v0[i]);
    s_end[0][k][cl] = v0[LCH - 1];

    // ---- prefetch half 1 BEFORE the barrier (in flight during combine) ----
    float v1[LCH];
    #pragma unroll
    for (int i = 0; i < LCH; i++)
        v1[i] = xp1[(long)i * TS];

    __syncthreads();   // barrier 1: s_end[0] visible; h1 loads in flight

    // ---- thread-parallel combine for half 0 ----
    // E = exclusive carry into chunk k: Horner fold of s_end[0][0..k-1][cl]
    float E = 0.0f;
    for (int m = 0; m < k; m++)
        E = fmaf(a16, E, s_end[0][m][cl]);
    if (k == NC - 1)
        s_c0[cl] = fmaf(a16, E, s_end[0][NC - 1][cl]);  // inclusive total of h0

    // ---- apply + store half 0 ----
    {
        float* __restrict__ op = out + base;
        float pw = a;
        #pragma unroll
        for (int i = 0; i < LCH; i++) {
            op[(long)i * TS] = fmaf(pw, E, v0[i]);
            pw *= a;
        }
    }

    // ---- half 1: local scan (loads already arrived/arriving) ----
    #pragma unroll
    for (int i = 1; i < LCH; i++)
        v1[i] = fmaf(a, v1[i - 1], v1[i]);
    s_end[1][k][cl] = v1[LCH - 1];

    __syncthreads();   // barrier 2: s_end[1] + s_c0 visible

    // ---- thread-parallel combine for half 1 (seeded by h0's total) ----
    float E1 = s_c0[cl];
    for (int m = 0; m < k; m++)
        E1 = fmaf(a16, E1, s_end[1][m][cl]);

    // ---- apply + store half 1 ----
    {
        float* __restrict__ op = out + base + (long)HALF * TS;
        float pw = a;
        #pragma unroll
        for (int i = 0; i < LCH; i++) {
            op[(long)i * TS] = fmaf(pw, E1, v1[i]);
            pw *= a;
        }
    }
}

extern "C" void kernel_launch(void* const* d_in, const int* in_sizes, int n_in,
                              void* d_out, int out_size)
{
    // Identify x vs A by element count (A has D=64 elements).
    const float* x = (const float*)d_in[0];
    const float* A = (const float*)d_in[1];
    long nx = in_sizes[0];
    if (n_in >= 2 && in_sizes[0] == D && in_sizes[1] > D) {
        x = (const float*)d_in[1];
        A = (const float*)d_in[0];
        nx = in_sizes[1];
    }
    const int B = (int)(nx / ((long)SEQ * D * D));   // 4

    dim3 grid(B * D * 2);
    dim3 block(TPB);
    ssm_scan_kernel<<<grid, block>>>(x, A, (float*)d_out);
}

// round 8
// speedup vs baseline: 1.2149x; 1.2149x over previous
#include <cuda_runtime.h>
#include <cuda_bf16.h>

// StateSpaceLayer: out[b,t,r,c] = sum_{j<=t} A[r]^(t-j) * x[b,j,r,c]
// == per-(b,r,c) linear recurrence y_t = A[r]*y_{t-1} + x_t.
// x, out: (B,SEQ,D,D) fp32; A: (D,) fp32.  B=4, SEQ=512, D=64.
//
// R8: float2 + 32-lane contiguous warp chunks + occ 2 (the never-tested cell).
// Halves LDG count and uses STG.64 (7.75 cyc vs 2x5) to cut LSU issue cost,
// which round-7 arithmetic showed is >half the kernel time.
// Block = one (b, r): 32 float2 lanes cover the full 64-c row (a = A[r] is
// block-uniform). 16 chunks x 8 timesteps per pass, 4 pipelined passes over
// seq=512; next pass's loads are issued before each barrier. Thread-parallel
// Horner carry combine; cross-pass carry via double-buffered s_tot.
// grid = 256 blocks, occ 2 -> whole grid resident in a single wave.

#define SEQ   512
#define D     64
#define LCH   8             // timesteps per chunk per pass (float2 regs)
#define NC    16            // chunks per pass
#define PASS_T (NC*LCH)     // 128 timesteps per pass
#define NPASS 4
#define TPB   (NC*32)       // 512 threads
#define TS2   ((D*D)/2)     // timestep stride in float2 = 2048

__global__ __launch_bounds__(TPB, 2)
void ssm_scan_kernel(const float2* __restrict__ x,
                     const float* __restrict__ A,
                     float2* __restrict__ out)
{
    // grid = B * D : block covers (b, r) and the full c-row
    const int bid = blockIdx.x;
    const int r   = bid & (D - 1);
    const int b   = bid >> 6;

    const int tid = threadIdx.x;
    const int l   = tid & 31;            // float2 lane: c = 2l, 2l+1
    const int k   = tid >> 5;            // chunk index 0..NC-1

    const float a = fmaxf(A[r], 1e-6f);  // reference clips at EPS=1e-6
    const float a2 = a * a;
    const float a4 = a2 * a2;
    const float a8 = a4 * a4;            // per-chunk decay (a^LCH)

    // float2 base for (b, t, r, 2l): index = (b*SEQ + t)*TS2 + r*32 + l
    const long rowoff = (long)r * 32 + l;
    const float2* __restrict__ xb = x + (long)b * SEQ * TS2 + rowoff;
    float2* __restrict__ ob       = out + (long)b * SEQ * TS2 + rowoff;

    __shared__ float2 s_end[2][NC][33];  // chunk-end partials (padded rows)
    __shared__ float2 s_tot[2][32];      // running carry across passes

    if (tid < 32) s_tot[1][tid] = make_float2(0.0f, 0.0f);

    // ---- prologue: load pass 0 ----
    float2 v[2][LCH];
    {
        const float2* __restrict__ xp = xb + (long)(k * LCH) * TS2;
        #pragma unroll
        for (int i = 0; i < LCH; i++)
            v[0][i] = xp[(long)i * TS2];
    }

    #pragma unroll
    for (int p = 0; p < NPASS; p++) {
        const int cur = p & 1;
        const int nxt = cur ^ 1;

        // ---- prefetch next pass BEFORE this pass's barrier ----
        if (p + 1 < NPASS) {
            const float2* __restrict__ xp =
                xb + (long)((p + 1) * PASS_T + k * LCH) * TS2;
            #pragma unroll
            for (int i = 0; i < LCH; i++)
                v[nxt][i] = xp[(long)i * TS2];
        }

        // ---- local inclusive scan of current pass ----
        #pragma unroll
        for (int i = 1; i < LCH; i++) {
            v[cur][i].x = fmaf(a, v[cur][i - 1].x, v[cur][i].x);
            v[cur][i].y = fmaf(a, v[cur][i - 1].y, v[cur][i].y);
        }
        s_end[cur][k][l] = v[cur][LCH - 1];

        __syncthreads();  // s_end[cur] + s_tot[(p+1)&1] visible; nxt loads in flight

        // ---- thread-parallel combine: exclusive carry into chunk k ----
        // seed = total carry from previous pass
        float2 E = s_tot[(p + 1) & 1][l];
        for (int m = 0; m < k; m++) {
            float2 e = s_end[cur][m][l];
            E.x = fmaf(a8, E.x, e.x);
            E.y = fmaf(a8, E.y, e.y);
        }
        if (k == NC - 1) {
            float2 e = s_end[cur][NC - 1][l];
            float2 T;
            T.x = fmaf(a8, E.x, e.x);
            T.y = fmaf(a8, E.y, e.y);
            s_tot[p & 1][l] = T;          // consumed after NEXT barrier
        }

        // ---- apply carry and store: out_i = v_i + a^(i+1) * E ----
        float2* __restrict__ op = ob + (long)(p * PASS_T + k * LCH) * TS2;
        float pw = a;
        #pragma unroll
        for (int i = 0; i < LCH; i++) {
            float2 o;
            o.x = fmaf(pw, E.x, v[cur][i].x);
            o.y = fmaf(pw, E.y, v[cur][i].y);
            op[(long)i * TS2] = o;
            pw *= a;
        }
    }
}

extern "C" void kernel_launch(void* const* d_in, const int* in_sizes, int n_in,
                              void* d_out, int out_size)
{
    // Identify x vs A by element count (A has D=64 elements).
    const float* x = (const float*)d_in[0];
    const float* A = (const float*)d_in[1];
    long nx = in_sizes[0];
    if (n_in >= 2 && in_sizes[0] == D && in_sizes[1] > D) {
        x = (const float*)d_in[1];
        A = (const float*)d_in[0];
        nx = in_sizes[1];
    }
    const int B = (int)(nx / ((long)SEQ * D * D));   // 4

    dim3 grid(B * D);
    dim3 block(TPB);
    ssm_scan_kernel<<<grid, block>>>((const float2*)x, A, (float2*)d_out);
}